// round 1
// baseline (speedup 1.0000x reference)
#include <cuda_runtime.h>
#include <cstdint>

// Problem constants
#define NN 50000
#define EE 600000
#define DD 128
#define HH 128
#define CC 64
#define LLAYERS 3
#define XCW (DD + LLAYERS * HH)   // 512

// ---------------- scratch (device globals; no runtime allocation) ----------
__device__ float g_deg[NN];
__device__ float g_dinv[NN];
__device__ float g_hW[(size_t)NN * HH];
__device__ float g_agg[(size_t)NN * HH];
__device__ float g_xc[(size_t)NN * XCW];
__device__ float g_z[(size_t)NN * HH];
__device__ float g_z2[(size_t)NN * CC];

// ---------------- small kernels --------------------------------------------
__global__ void k_init_deg() {
    int i = blockIdx.x * blockDim.x + threadIdx.x;
    if (i < NN) g_deg[i] = 1.0f;   // self-loop
}

__global__ void k_count_deg(const int* __restrict__ ei) {
    int e = blockIdx.x * blockDim.x + threadIdx.x;
    if (e < EE) atomicAdd(&g_deg[ei[EE + e]], 1.0f);
}

__global__ void k_dinv() {
    int i = blockIdx.x * blockDim.x + threadIdx.x;
    if (i < NN) g_dinv[i] = rsqrtf(g_deg[i]);
}

// copy x (N x 128) into xc[:, 0:128] (row stride 512)
__global__ void k_copy_x(const float* __restrict__ x) {
    int idx = blockIdx.x * blockDim.x + threadIdx.x;   // float4 index
    if (idx >= NN * 32) return;
    int n = idx >> 5;
    int c = idx & 31;
    ((float4*)g_xc)[(size_t)n * (XCW / 4) + c] = ((const float4*)x)[idx];
}

// agg = hW * dinv^2 (self-loop term)
__global__ void k_selfinit() {
    int idx = blockIdx.x * blockDim.x + threadIdx.x;   // float4 index
    if (idx >= NN * 32) return;
    int n = idx >> 5;
    float di = g_dinv[n];
    float c = di * di;
    float4 v = ((const float4*)g_hW)[idx];
    v.x *= c; v.y *= c; v.z *= c; v.w *= c;
    ((float4*)g_agg)[idx] = v;
}

// one warp per edge: agg[dst] += hW[src] * dinv[src]*dinv[dst]
__global__ void k_scatter(const int* __restrict__ ei) {
    int t = blockIdx.x * blockDim.x + threadIdx.x;
    int w = t >> 5;
    if (w >= EE) return;
    int lane = t & 31;
    int s = ei[w];
    int d = ei[EE + w];
    float coef = g_dinv[s] * g_dinv[d];
    float4 v = ((const float4*)(g_hW + (size_t)s * HH))[lane];
    v.x *= coef; v.y *= coef; v.z *= coef; v.w *= coef;
    float* dp = g_agg + (size_t)d * HH + lane * 4;
    asm volatile("red.global.add.v4.f32 [%0], {%1,%2,%3,%4};"
                 :: "l"(dp), "f"(v.x), "f"(v.y), "f"(v.z), "f"(v.w)
                 : "memory");
}

// one warp per node: h = relu(LN(agg + bg)) -> xc[:, (1+layer)*128 ...]
__global__ void k_ln_relu(const float* __restrict__ bg,
                          const float* __restrict__ lng,
                          const float* __restrict__ lnb,
                          int layer) {
    int t = blockIdx.x * blockDim.x + threadIdx.x;
    int w = t >> 5;
    if (w >= NN) return;
    int lane = t & 31;
    float4 v = ((const float4*)g_agg)[(size_t)w * 32 + lane];
    float4 bb = ((const float4*)(bg + layer * HH))[lane];
    v.x += bb.x; v.y += bb.y; v.z += bb.z; v.w += bb.w;

    float s = v.x + v.y + v.z + v.w;
    #pragma unroll
    for (int o = 16; o; o >>= 1) s += __shfl_xor_sync(0xffffffffu, s, o);
    float mu = s * (1.0f / HH);

    float dx = v.x - mu, dy = v.y - mu, dz = v.z - mu, dw = v.w - mu;
    float q = dx * dx + dy * dy + dz * dz + dw * dw;
    #pragma unroll
    for (int o = 16; o; o >>= 1) q += __shfl_xor_sync(0xffffffffu, q, o);
    float inv = rsqrtf(q * (1.0f / HH) + 1e-5f);

    float4 g4 = ((const float4*)(lng + layer * HH))[lane];
    float4 b4 = ((const float4*)(lnb + layer * HH))[lane];
    float4 o4;
    o4.x = fmaxf(fmaf(g4.x * dx, inv, b4.x), 0.0f);
    o4.y = fmaxf(fmaf(g4.y * dy, inv, b4.y), 0.0f);
    o4.z = fmaxf(fmaf(g4.z * dz, inv, b4.z), 0.0f);
    o4.w = fmaxf(fmaf(g4.w * dw, inv, b4.w), 0.0f);
    ((float4*)g_xc)[(size_t)w * (XCW / 4) + (1 + layer) * 32 + lane] = o4;
}

// one warp per node: softmax over 64 (2 cols/thread)
__global__ void k_softmax(float* __restrict__ out) {
    int t = blockIdx.x * blockDim.x + threadIdx.x;
    int w = t >> 5;
    if (w >= NN) return;
    int lane = t & 31;
    float2 v = ((const float2*)g_z2)[(size_t)w * 32 + lane];
    float m = fmaxf(v.x, v.y);
    #pragma unroll
    for (int o = 16; o; o >>= 1) m = fmaxf(m, __shfl_xor_sync(0xffffffffu, m, o));
    float e0 = __expf(v.x - m);
    float e1 = __expf(v.y - m);
    float s = e0 + e1;
    #pragma unroll
    for (int o = 16; o; o >>= 1) s += __shfl_xor_sync(0xffffffffu, s, o);
    float inv = 1.0f / s;
    ((float2*)out)[(size_t)w * 32 + lane] = make_float2(e0 * inv, e1 * inv);
}

// ---------------- SGEMM -----------------------------------------------------
// C[M,Ncols] = A[M,K] @ B[K,Ncols] (+bias, relu). A/C selected from globals.
// a_sel: 0 = g_xc (+a_off), 1 = g_z.  c_sel: 0 = g_hW, 1 = g_z, 2 = g_z2.
template <int BM, int BN, int BK, int TM, int TN, bool BIAS, bool RELU>
__global__ __launch_bounds__(256) void k_gemm(
    int a_sel, int a_off, int lda,
    const float* __restrict__ B, int ldb,
    const float* __restrict__ bias,
    int c_sel, int ldc, int M, int K) {

    const float* A = ((a_sel == 0) ? g_xc : g_z) + a_off;
    float* Cmat = (c_sel == 0) ? g_hW : ((c_sel == 1) ? g_z : g_z2);

    __shared__ float As[BK][BM];
    __shared__ float Bs[BK][BN];

    int tid = threadIdx.x;
    int brow = blockIdx.x * BM;
    int bcol = blockIdx.y * BN;
    int tcol = tid % (BN / TN);
    int trow = tid / (BN / TN);

    float acc[TM][TN];
    #pragma unroll
    for (int m = 0; m < TM; m++)
        #pragma unroll
        for (int n = 0; n < TN; n++) acc[m][n] = 0.0f;

    // A loader: BM*BK floats as float4 along K
    int a_row = tid / (BK / 4);
    int a_k = (tid % (BK / 4)) * 4;

    for (int k0 = 0; k0 < K; k0 += BK) {
        int gr = brow + a_row;
        float4 av = make_float4(0.f, 0.f, 0.f, 0.f);
        if (gr < M) av = *(const float4*)(A + (size_t)gr * lda + k0 + a_k);
        As[a_k + 0][a_row] = av.x;
        As[a_k + 1][a_row] = av.y;
        As[a_k + 2][a_row] = av.z;
        As[a_k + 3][a_row] = av.w;
        #pragma unroll
        for (int i = 0; i < (BK * BN) / 256; i++) {
            int idx = i * 256 + tid;
            int br = idx / BN, bc = idx % BN;
            Bs[br][bc] = B[(size_t)(k0 + br) * ldb + bcol + bc];
        }
        __syncthreads();
        #pragma unroll
        for (int k = 0; k < BK; k++) {
            float a[TM], b[TN];
            #pragma unroll
            for (int m = 0; m < TM; m++) a[m] = As[k][trow * TM + m];
            #pragma unroll
            for (int n = 0; n < TN; n++) b[n] = Bs[k][tcol * TN + n];
            #pragma unroll
            for (int m = 0; m < TM; m++)
                #pragma unroll
                for (int n = 0; n < TN; n++) acc[m][n] = fmaf(a[m], b[n], acc[m][n]);
        }
        __syncthreads();
    }

    #pragma unroll
    for (int m = 0; m < TM; m++) {
        int gr = brow + trow * TM + m;
        if (gr >= M) continue;
        #pragma unroll
        for (int n = 0; n < TN; n++) {
            int gc = bcol + tcol * TN + n;
            float v = acc[m][n];
            if (BIAS) v += bias[gc];
            if (RELU) v = fmaxf(v, 0.0f);
            Cmat[(size_t)gr * ldc + gc] = v;
        }
    }
}

// ---------------- launch -----------------------------------------------------
extern "C" void kernel_launch(void* const* d_in, const int* in_sizes, int n_in,
                              void* d_out, int out_size) {
    const float* x      = (const float*)d_in[0];
    const int*   ei     = (const int*)d_in[1];
    const float* Wg     = (const float*)d_in[2];
    const float* bg     = (const float*)d_in[3];
    const float* ln_g   = (const float*)d_in[4];
    const float* ln_b   = (const float*)d_in[5];
    const float* mlp_W1 = (const float*)d_in[6];
    const float* mlp_b1 = (const float*)d_in[7];
    const float* mlp_W2 = (const float*)d_in[8];
    const float* mlp_b2 = (const float*)d_in[9];
    float* out = (float*)d_out;

    const int TB = 256;
    int gN     = (NN + TB - 1) / TB;
    int gE     = (EE + TB - 1) / TB;
    int gN32   = (NN * 32 + TB - 1) / TB;   // warp-per-node / float4-per-node grids
    int gE32   = (EE * 32 + TB - 1) / TB;   // warp-per-edge

    k_init_deg<<<gN, TB>>>();
    k_count_deg<<<gE, TB>>>(ei);
    k_dinv<<<gN, TB>>>();
    k_copy_x<<<gN32, TB>>>(x);

    dim3 ggemm((NN + 127) / 128, 1);

    for (int i = 0; i < LLAYERS; i++) {
        // hW = h @ Wg[i]    (h = xc[:, i*128:(i+1)*128], lda=512)
        k_gemm<128, 128, 8, 8, 8, false, false><<<ggemm, TB>>>(
            0, i * HH, XCW, Wg + (size_t)i * DD * HH, HH, nullptr,
            0, HH, NN, DD);
        k_selfinit<<<gN32, TB>>>();
        k_scatter<<<gE32, TB>>>(ei);
        k_ln_relu<<<gN32, TB>>>(bg, ln_g, ln_b, i);
    }

    // z = relu(xc @ W1 + b1)
    k_gemm<128, 128, 8, 8, 8, true, true><<<ggemm, TB>>>(
        0, 0, XCW, mlp_W1, HH, mlp_b1, 1, HH, NN, XCW);

    // z2 = z @ W2 + b2
    k_gemm<128, 64, 8, 8, 4, true, false><<<ggemm, TB>>>(
        1, 0, HH, mlp_W2, CC, mlp_b2, 2, CC, NN, HH);

    k_softmax<<<gN32, TB>>>(out);
}

// round 3
// speedup vs baseline: 1.6821x; 1.6821x over previous
#include <cuda_runtime.h>
#include <cuda_bf16.h>
#include <cstdint>

// Problem constants
#define NN 50000
#define EE 600000
#define DD 128
#define HH 128
#define CC 64
#define LLAYERS 3
#define XCW (DD + LLAYERS * HH)   // 512

// ---------------- scratch (device globals; no runtime allocation) ----------
__device__ float g_deg[NN];
__device__ float g_dinv[NN];
__device__ float g_hW[(size_t)NN * HH];
__device__ float g_agg[(size_t)NN * HH];
__device__ float g_xc[(size_t)NN * XCW];
__device__ float g_z[(size_t)NN * HH];
__device__ float g_z2[(size_t)NN * CC];

// ---------------- small kernels --------------------------------------------
__global__ void k_init_deg() {
    int i = blockIdx.x * blockDim.x + threadIdx.x;
    if (i < NN) g_deg[i] = 1.0f;   // self-loop
}

__global__ void k_count_deg(const int* __restrict__ ei) {
    int e = blockIdx.x * blockDim.x + threadIdx.x;
    if (e < EE) atomicAdd(&g_deg[ei[EE + e]], 1.0f);
}

__global__ void k_dinv() {
    int i = blockIdx.x * blockDim.x + threadIdx.x;
    if (i < NN) g_dinv[i] = rsqrtf(g_deg[i]);
}

__global__ void k_copy_x(const float* __restrict__ x) {
    int idx = blockIdx.x * blockDim.x + threadIdx.x;   // float4 index
    if (idx >= NN * 32) return;
    int n = idx >> 5;
    int c = idx & 31;
    ((float4*)g_xc)[(size_t)n * (XCW / 4) + c] = ((const float4*)x)[idx];
}

__global__ void k_selfinit() {
    int idx = blockIdx.x * blockDim.x + threadIdx.x;   // float4 index
    if (idx >= NN * 32) return;
    int n = idx >> 5;
    float di = g_dinv[n];
    float c = di * di;
    float4 v = ((const float4*)g_hW)[idx];
    v.x *= c; v.y *= c; v.z *= c; v.w *= c;
    ((float4*)g_agg)[idx] = v;
}

// one warp per edge: agg[dst] += hW[src] * dinv[src]*dinv[dst]
__global__ void k_scatter(const int* __restrict__ ei) {
    int t = blockIdx.x * blockDim.x + threadIdx.x;
    int w = t >> 5;
    if (w >= EE) return;
    int lane = t & 31;
    int s = ei[w];
    int d = ei[EE + w];
    float coef = g_dinv[s] * g_dinv[d];
    float4 v = ((const float4*)(g_hW + (size_t)s * HH))[lane];
    v.x *= coef; v.y *= coef; v.z *= coef; v.w *= coef;
    float* dp = g_agg + (size_t)d * HH + lane * 4;
    asm volatile("red.global.add.v4.f32 [%0], {%1,%2,%3,%4};"
                 :: "l"(dp), "f"(v.x), "f"(v.y), "f"(v.z), "f"(v.w)
                 : "memory");
}

// one warp per node: h = relu(LN(agg + bg)) -> xc[:, (1+layer)*128 ...]
__global__ void k_ln_relu(const float* __restrict__ bg,
                          const float* __restrict__ lng,
                          const float* __restrict__ lnb,
                          int layer) {
    int t = blockIdx.x * blockDim.x + threadIdx.x;
    int w = t >> 5;
    if (w >= NN) return;
    int lane = t & 31;
    float4 v = ((const float4*)g_agg)[(size_t)w * 32 + lane];
    float4 bb = ((const float4*)(bg + layer * HH))[lane];
    v.x += bb.x; v.y += bb.y; v.z += bb.z; v.w += bb.w;

    float s = v.x + v.y + v.z + v.w;
    #pragma unroll
    for (int o = 16; o; o >>= 1) s += __shfl_xor_sync(0xffffffffu, s, o);
    float mu = s * (1.0f / HH);

    float dx = v.x - mu, dy = v.y - mu, dz = v.z - mu, dw = v.w - mu;
    float q = dx * dx + dy * dy + dz * dz + dw * dw;
    #pragma unroll
    for (int o = 16; o; o >>= 1) q += __shfl_xor_sync(0xffffffffu, q, o);
    float inv = rsqrtf(q * (1.0f / HH) + 1e-5f);

    float4 g4 = ((const float4*)(lng + layer * HH))[lane];
    float4 b4 = ((const float4*)(lnb + layer * HH))[lane];
    float4 o4;
    o4.x = fmaxf(fmaf(g4.x * dx, inv, b4.x), 0.0f);
    o4.y = fmaxf(fmaf(g4.y * dy, inv, b4.y), 0.0f);
    o4.z = fmaxf(fmaf(g4.z * dz, inv, b4.z), 0.0f);
    o4.w = fmaxf(fmaf(g4.w * dw, inv, b4.w), 0.0f);
    ((float4*)g_xc)[(size_t)w * (XCW / 4) + (1 + layer) * 32 + lane] = o4;
}

// one warp per node: softmax over 64 (2 cols/thread)
__global__ void k_softmax(float* __restrict__ out) {
    int t = blockIdx.x * blockDim.x + threadIdx.x;
    int w = t >> 5;
    if (w >= NN) return;
    int lane = t & 31;
    float2 v = ((const float2*)g_z2)[(size_t)w * 32 + lane];
    float m = fmaxf(v.x, v.y);
    #pragma unroll
    for (int o = 16; o; o >>= 1) m = fmaxf(m, __shfl_xor_sync(0xffffffffu, m, o));
    float e0 = __expf(v.x - m);
    float e1 = __expf(v.y - m);
    float s = e0 + e1;
    #pragma unroll
    for (int o = 16; o; o >>= 1) s += __shfl_xor_sync(0xffffffffu, s, o);
    float inv = 1.0f / s;
    ((float2*)out)[(size_t)w * 32 + lane] = make_float2(e0 * inv, e1 * inv);
}

// ==================== bf16-split mma.sync GEMM ==============================
// C[M,BN] = A[M,K] @ B[K,BN]; A fp32 (g_xc/g_z), B fp32 weights.
// 3-term bf16 split: hi*hi + hi*lo + lo*hi, fp32 accumulate.
// CTA: 256 thr (8 warps, 2x4), tile 128xBN, BK=32 chunks.

__device__ __forceinline__ uint32_t smem_u32(const void* p) {
    uint32_t a;
    asm("{ .reg .u64 t; cvta.to.shared.u64 t, %1; cvt.u32.u64 %0, t; }"
        : "=r"(a) : "l"(p));
    return a;
}

__device__ __forceinline__ void ldm_x4(uint32_t* r, uint32_t addr) {
    asm volatile("ldmatrix.sync.aligned.m8n8.x4.shared.b16 {%0,%1,%2,%3}, [%4];"
                 : "=r"(r[0]), "=r"(r[1]), "=r"(r[2]), "=r"(r[3]) : "r"(addr));
}

__device__ __forceinline__ void ldm_x4_t(uint32_t* r, uint32_t addr) {
    asm volatile("ldmatrix.sync.aligned.m8n8.x4.trans.shared.b16 {%0,%1,%2,%3}, [%4];"
                 : "=r"(r[0]), "=r"(r[1]), "=r"(r[2]), "=r"(r[3]) : "r"(addr));
}

__device__ __forceinline__ void mma_bf16(float* d, const uint32_t* a, const uint32_t* b) {
    asm volatile("mma.sync.aligned.m16n8k16.row.col.f32.bf16.bf16.f32 "
                 "{%0,%1,%2,%3}, {%4,%5,%6,%7}, {%8,%9}, {%0,%1,%2,%3};"
                 : "+f"(d[0]), "+f"(d[1]), "+f"(d[2]), "+f"(d[3])
                 : "r"(a[0]), "r"(a[1]), "r"(a[2]), "r"(a[3]),
                   "r"(b[0]), "r"(b[1]));
}

template <int BN, bool BIAS, bool RELU>
__global__ __launch_bounds__(256) void k_gemm_mma(
    int a_sel, int a_off, int lda,
    const float* __restrict__ B, int ldb,
    const float* __restrict__ bias,
    int c_sel, int ldc, int M, int nk) {

    constexpr int WN = BN / 4;       // warp n-tile: 32 or 16
    constexpr int NFRAG = WN / 8;    // 4 or 2
    constexpr int LDA_S = 40;        // 32 + 8 pad (bf16)
    constexpr int LDB_S = BN + 8;

    __shared__ __align__(16) __nv_bfloat16 As[2][128][LDA_S];
    __shared__ __align__(16) __nv_bfloat16 Bs[2][32][LDB_S];

    const float* A = ((a_sel == 0) ? g_xc : g_z) + a_off;
    float* Cmat = (c_sel == 0) ? g_hW : ((c_sel == 1) ? g_z : g_z2);

    int tid = threadIdx.x;
    int wid = tid >> 5;
    int lane = tid & 31;
    int warp_m = wid >> 2;           // 0..1
    int warp_n = wid & 3;            // 0..3
    int row0 = blockIdx.x * 128;

    uint32_t asb = smem_u32(As);
    uint32_t bsb = smem_u32(Bs);

    float d[4][NFRAG][4];
    #pragma unroll
    for (int mf = 0; mf < 4; mf++)
        #pragma unroll
        for (int nf = 0; nf < NFRAG; nf++)
            #pragma unroll
            for (int j = 0; j < 4; j++) d[mf][nf][j] = 0.0f;

    for (int ck = 0; ck < nk; ck++) {
        int k0 = ck * 32;

        // ---- A chunk: 128 rows x 32 cols fp32 -> bf16 hi/lo ----
        #pragma unroll
        for (int j = 0; j < 4; j++) {
            int i = tid + j * 256;         // float4 index, 0..1023
            int r = i >> 3;
            int c4 = (i & 7) << 2;
            float4 v = make_float4(0.f, 0.f, 0.f, 0.f);
            int gr = row0 + r;
            if (gr < M) v = *(const float4*)(A + (size_t)gr * lda + k0 + c4);
            __nv_bfloat162 h0 = __float22bfloat162_rn(make_float2(v.x, v.y));
            __nv_bfloat162 h1 = __float22bfloat162_rn(make_float2(v.z, v.w));
            float2 f0 = __bfloat1622float2(h0);
            float2 f1 = __bfloat1622float2(h1);
            __nv_bfloat162 l0 = __float22bfloat162_rn(make_float2(v.x - f0.x, v.y - f0.y));
            __nv_bfloat162 l1 = __float22bfloat162_rn(make_float2(v.z - f1.x, v.w - f1.y));
            *(__nv_bfloat162*)&As[0][r][c4]     = h0;
            *(__nv_bfloat162*)&As[0][r][c4 + 2] = h1;
            *(__nv_bfloat162*)&As[1][r][c4]     = l0;
            *(__nv_bfloat162*)&As[1][r][c4 + 2] = l1;
        }

        // ---- B chunk: 32 rows x BN cols fp32 -> bf16 hi/lo ----
        #pragma unroll
        for (int j = 0; j < (32 * BN / 4) / 256; j++) {
            int i = tid + j * 256;
            int kk = i / (BN / 4);
            int n4 = (i % (BN / 4)) << 2;
            float4 v = *(const float4*)(B + (size_t)(k0 + kk) * ldb + n4);
            __nv_bfloat162 h0 = __float22bfloat162_rn(make_float2(v.x, v.y));
            __nv_bfloat162 h1 = __float22bfloat162_rn(make_float2(v.z, v.w));
            float2 f0 = __bfloat1622float2(h0);
            float2 f1 = __bfloat1622float2(h1);
            __nv_bfloat162 l0 = __float22bfloat162_rn(make_float2(v.x - f0.x, v.y - f0.y));
            __nv_bfloat162 l1 = __float22bfloat162_rn(make_float2(v.z - f1.x, v.w - f1.y));
            *(__nv_bfloat162*)&Bs[0][kk][n4]     = h0;
            *(__nv_bfloat162*)&Bs[0][kk][n4 + 2] = h1;
            *(__nv_bfloat162*)&Bs[1][kk][n4]     = l0;
            *(__nv_bfloat162*)&Bs[1][kk][n4 + 2] = l1;
        }
        __syncthreads();

        // ---- compute: 2 k16 steps ----
        #pragma unroll
        for (int ks = 0; ks < 2; ks++) {
            int kb = ks * 16;
            uint32_t a[2][4][4];
            #pragma unroll
            for (int h = 0; h < 2; h++)
                #pragma unroll
                for (int mf = 0; mf < 4; mf++) {
                    int rr = warp_m * 64 + mf * 16 + (lane & 7) + ((lane >> 3) & 1) * 8;
                    int cc = kb + (lane >> 4) * 8;
                    ldm_x4(a[h][mf],
                           asb + (uint32_t)(h * 128 * LDA_S + rr * LDA_S + cc) * 2);
                }
            uint32_t b[2][NFRAG][2];
            #pragma unroll
            for (int h = 0; h < 2; h++)
                #pragma unroll
                for (int nf2 = 0; nf2 < NFRAG / 2; nf2++) {
                    int kr = kb + ((lane >> 3) & 1) * 8 + (lane & 7);
                    int nc = warp_n * WN + nf2 * 16 + (lane >> 4) * 8;
                    uint32_t r4[4];
                    ldm_x4_t(r4, bsb + (uint32_t)(h * 32 * LDB_S + kr * LDB_S + nc) * 2);
                    b[h][nf2 * 2][0] = r4[0]; b[h][nf2 * 2][1] = r4[1];
                    b[h][nf2 * 2 + 1][0] = r4[2]; b[h][nf2 * 2 + 1][1] = r4[3];
                }
            #pragma unroll
            for (int mf = 0; mf < 4; mf++)
                #pragma unroll
                for (int nf = 0; nf < NFRAG; nf++) {
                    mma_bf16(d[mf][nf], a[0][mf], b[0][nf]);   // hi*hi
                    mma_bf16(d[mf][nf], a[0][mf], b[1][nf]);   // hi*lo
                    mma_bf16(d[mf][nf], a[1][mf], b[0][nf]);   // lo*hi
                }
        }
        __syncthreads();
    }

    // ---- epilogue ----
    #pragma unroll
    for (int mf = 0; mf < 4; mf++) {
        int rbase = row0 + warp_m * 64 + mf * 16 + (lane >> 2);
        #pragma unroll
        for (int half = 0; half < 2; half++) {
            int gr = rbase + half * 8;
            if (gr < M) {
                #pragma unroll
                for (int nf = 0; nf < NFRAG; nf++) {
                    int gc = warp_n * WN + nf * 8 + (lane & 3) * 2;
                    float2 v = make_float2(d[mf][nf][half * 2], d[mf][nf][half * 2 + 1]);
                    if (BIAS) { v.x += bias[gc]; v.y += bias[gc + 1]; }
                    if (RELU) { v.x = fmaxf(v.x, 0.f); v.y = fmaxf(v.y, 0.f); }
                    *(float2*)(Cmat + (size_t)gr * ldc + gc) = v;
                }
            }
        }
    }
}

// ---------------- launch -----------------------------------------------------
extern "C" void kernel_launch(void* const* d_in, const int* in_sizes, int n_in,
                              void* d_out, int out_size) {
    const float* x      = (const float*)d_in[0];
    const int*   ei     = (const int*)d_in[1];
    const float* Wg     = (const float*)d_in[2];
    const float* bg     = (const float*)d_in[3];
    const float* ln_g   = (const float*)d_in[4];
    const float* ln_b   = (const float*)d_in[5];
    const float* mlp_W1 = (const float*)d_in[6];
    const float* mlp_b1 = (const float*)d_in[7];
    const float* mlp_W2 = (const float*)d_in[8];
    const float* mlp_b2 = (const float*)d_in[9];
    float* out = (float*)d_out;

    const int TB = 256;
    int gN   = (NN + TB - 1) / TB;
    int gE   = (EE + TB - 1) / TB;
    int gN32 = (NN * 32 + TB - 1) / TB;
    int gE32 = (EE * 32 + TB - 1) / TB;

    k_init_deg<<<gN, TB>>>();
    k_count_deg<<<gE, TB>>>(ei);
    k_dinv<<<gN, TB>>>();
    k_copy_x<<<gN32, TB>>>(x);

    int gM = (NN + 127) / 128;   // 391

    for (int i = 0; i < LLAYERS; i++) {
        // hW = h @ Wg[i]   (h = xc[:, i*128:(i+1)*128], lda=512), K=128 -> nk=4
        k_gemm_mma<128, false, false><<<gM, TB>>>(
            0, i * HH, XCW, Wg + (size_t)i * DD * HH, HH, nullptr,
            0, HH, NN, 4);
        k_selfinit<<<gN32, TB>>>();
        k_scatter<<<gE32, TB>>>(ei);
        k_ln_relu<<<gN32, TB>>>(bg, ln_g, ln_b, i);
    }

    // z = relu(xc @ W1 + b1)   K=512 -> nk=16
    k_gemm_mma<128, true, true><<<gM, TB>>>(
        0, 0, XCW, mlp_W1, HH, mlp_b1, 1, HH, NN, 16);

    // z2 = z @ W2 + b2         K=128 -> nk=4
    k_gemm_mma<64, true, false><<<gM, TB>>>(
        1, 0, HH, mlp_W2, CC, mlp_b2, 2, CC, NN, 4);

    k_softmax<<<gN32, TB>>>(out);
}